// round 12
// baseline (speedup 1.0000x reference)
#include <cuda_runtime.h>
#include <cuda_bf16.h>
#include <math.h>
#include <stdint.h>

#define B_ 16384
#define D_ 4096
#define H_ 2048
#define E_ 64
#define K_ 2
#define TEMP_INV 1.25f   // 1/0.8

// ---------------------------------------------------------------------------
// Scratch (device globals; no allocs allowed)
// ---------------------------------------------------------------------------
__device__ float g_ent[B_ / 64];
__device__ __nv_bfloat16 g_xs[(size_t)B_ * 2 * D_];    // x split  [B][hi D|lo D]
__device__ __nv_bfloat16 g_ws[(size_t)H_ * 2 * D_];    // W1 split [H][hi D|lo D]
__device__ __nv_bfloat16 g_hs[(size_t)B_ * 2 * H_];    // h split  [B][hi H|lo H]
__device__ __nv_bfloat16 g_w2s[(size_t)E_ * 2 * H_];   // W2 split [E][hi H|lo H]

// ---------------------------------------------------------------------------
// Split helpers: 2-way bf16 decomposition v = hi + lo
// ---------------------------------------------------------------------------
__device__ __forceinline__ void split2(float v, uint16_t& h, uint16_t& l) {
    __nv_bfloat16 hb = __float2bfloat16_rn(v);
    float r = v - __bfloat162float(hb);
    __nv_bfloat16 lb = __float2bfloat16_rn(r);
    h = __bfloat16_as_ushort(hb);
    l = __bfloat16_as_ushort(lb);
}

__device__ __forceinline__ void split2_body(const float* __restrict__ src,
                                            __nv_bfloat16* __restrict__ dst,
                                            int rows, int cols,
                                            int bid, int nblocks) {
    const size_t n4 = (size_t)rows * cols / 4;
    for (size_t i = (size_t)bid * blockDim.x + threadIdx.x; i < n4;
         i += (size_t)nblocks * blockDim.x) {
        const int r = (int)(i / (cols / 4));
        const int c = (int)(i % (cols / 4)) * 4;
        float4 v = *(const float4*)(src + (size_t)r * cols + c);
        uint16_t h[4], l[4];
        split2(v.x, h[0], l[0]);
        split2(v.y, h[1], l[1]);
        split2(v.z, h[2], l[2]);
        split2(v.w, h[3], l[3]);
        __nv_bfloat16* row = dst + (size_t)r * (2 * cols);
        uint2 uh = {(uint32_t)h[0] | ((uint32_t)h[1] << 16),
                    (uint32_t)h[2] | ((uint32_t)h[3] << 16)};
        uint2 ul = {(uint32_t)l[0] | ((uint32_t)l[1] << 16),
                    (uint32_t)l[2] | ((uint32_t)l[3] << 16)};
        *(uint2*)(row + c)        = uh;
        *(uint2*)(row + cols + c) = ul;
    }
}

#define SPLIT_XB 2048
#define SPLIT_W1 248
#define SPLIT_NB 2304   // x:2048, W1:248, W2:8
__global__ __launch_bounds__(256) void split_both_kernel(
    const float* __restrict__ x, const float* __restrict__ W1,
    const float* __restrict__ W2) {
    if (blockIdx.x < SPLIT_XB)
        split2_body(x, g_xs, B_, D_, blockIdx.x, SPLIT_XB);
    else if (blockIdx.x < SPLIT_XB + SPLIT_W1)
        split2_body(W1, g_ws, H_, D_, blockIdx.x - SPLIT_XB, SPLIT_W1);
    else
        split2_body(W2, g_w2s, E_, H_, blockIdx.x - SPLIT_XB - SPLIT_W1,
                    SPLIT_NB - SPLIT_XB - SPLIT_W1);
}

// ---------------------------------------------------------------------------
// Common MMA / async primitives
// ---------------------------------------------------------------------------
__device__ __forceinline__ void cp16(uint32_t smem, const void* g) {
    asm volatile("cp.async.cg.shared.global [%0], [%1], 16;"
                 :: "r"(smem), "l"(g) : "memory");
}
#define CP_COMMIT() asm volatile("cp.async.commit_group;" ::: "memory")
#define CP_WAIT1()  asm volatile("cp.async.wait_group 1;" ::: "memory")
#define CP_WAIT2()  asm volatile("cp.async.wait_group 2;" ::: "memory")

__device__ __forceinline__ void ldmatrix4(uint32_t& r0, uint32_t& r1,
                                          uint32_t& r2, uint32_t& r3, uint32_t a) {
    asm volatile("ldmatrix.sync.aligned.m8n8.x4.shared.b16 {%0,%1,%2,%3}, [%4];"
                 : "=r"(r0), "=r"(r1), "=r"(r2), "=r"(r3) : "r"(a));
}

__device__ __forceinline__ void mma16816(float* c, uint32_t a0, uint32_t a1,
                                         uint32_t a2, uint32_t a3,
                                         uint32_t b0, uint32_t b1) {
    asm volatile(
        "mma.sync.aligned.m16n8k16.row.col.f32.bf16.bf16.f32 "
        "{%0,%1,%2,%3}, {%4,%5,%6,%7}, {%8,%9}, {%0,%1,%2,%3};"
        : "+f"(c[0]), "+f"(c[1]), "+f"(c[2]), "+f"(c[3])
        : "r"(a0), "r"(a1), "r"(a2), "r"(a3), "r"(b0), "r"(b1));
}

__device__ __forceinline__ uint32_t smem_u32(const void* p) {
    uint32_t a;
    asm("{ .reg .u64 t; cvta.to.shared.u64 t, %1; cvt.u32.u64 %0, t; }"
        : "=r"(a) : "l"(p));
    return a;
}

// ---------------------------------------------------------------------------
// GEMM1: h = relu(xh*wh + xh*wl + xl*wh + b1), flat 3-pass.
// CTA 128x256, KT=64, 3-stage cp.async, 8 warps of 64x64 tiles (1 CTA/SM).
// Halves x global traffic vs 128x128 and trims STS share on the smem port.
// Epilogue stores h as split bf16 pair into g_hs.
// ---------------------------------------------------------------------------
#define TM 128
#define TN 256
#define KT 64
#define NSTAGE 3
#define ROWB 144
#define STAGE_B (384 * ROWB)            // A 128 rows + B 256 rows = 55296
#define GEMM_SMEM (NSTAGE * STAGE_B)    // 165888
#define NPASS 3
#define NT (NPASS * (D_ / KT))          // 192

__device__ __forceinline__ void load_tile(uint32_t sbase, int kt, int st,
                                          int bm, int bn, int tid) {
    const int pass = kt >> 6;
    const int kk   = kt & 63;
    const int aoff = (pass == 2) ? D_ : 0;   // xl on pass 2
    const int boff = (pass == 1) ? D_ : 0;   // wl on pass 1
    const uint32_t stA = sbase + st * STAGE_B;
    const uint32_t stB = stA + 128 * ROWB;
#pragma unroll
    for (int j = 0; j < 12; j++) {
        const int c = tid + (j << 8);         // 0..3071 (256 threads x 12)
        const int r   = c >> 3;               // 0..383
        const int seg = c & 7;
        const int col = kk * KT + seg * 8;
        if (r < 128) {
            const __nv_bfloat16* g = g_xs + (size_t)(bm + r) * (2 * D_) + aoff + col;
            cp16(stA + r * ROWB + seg * 16, g);
        } else {
            const __nv_bfloat16* g = g_ws + (size_t)(bn + r - 128) * (2 * D_) + boff + col;
            cp16(stB + (r - 128) * ROWB + seg * 16, g);
        }
    }
}

__global__ __launch_bounds__(256, 1) void gemm1_mma_kernel(const float* __restrict__ b1) {
    extern __shared__ char smem[];
    const uint32_t sbase = smem_u32(smem);
    const int tid  = threadIdx.x;
    const int wid  = tid >> 5;
    const int lane = tid & 31;
    const int bm = blockIdx.x * TM;
    const int bn = blockIdx.y * TN;
    const int wm = (wid & 1) * 64;      // 2 warps in M
    const int wn = (wid >> 1) * 64;     // 4 warps in N

    float acc[4][8][4];
#pragma unroll
    for (int i = 0; i < 4; i++)
#pragma unroll
        for (int j = 0; j < 8; j++)
#pragma unroll
            for (int k = 0; k < 4; k++) acc[i][j][k] = 0.0f;

    load_tile(sbase, 0, 0, bm, bn, tid); CP_COMMIT();
    load_tile(sbase, 1, 1, bm, bn, tid); CP_COMMIT();

    const int aRow  = wm + (lane & 15);
    const int aColB = (lane >> 4) * 16;
    const int bRow  = wn + (lane & 7) + ((lane >> 4) & 1) * 8;
    const int bColB = ((lane >> 3) & 1) * 16;
    uint32_t aOff[4], bOff[4];
#pragma unroll
    for (int tm = 0; tm < 4; tm++) aOff[tm] = (aRow + tm * 16) * ROWB + aColB;
#pragma unroll
    for (int tp = 0; tp < 4; tp++) bOff[tp] = 128 * ROWB + (bRow + tp * 16) * ROWB + bColB;

    CP_WAIT1();
    __syncthreads();

    int st = 0, ldst = 2;
    for (int kt = 0; kt < NT; kt++) {
        if (kt + 2 < NT) load_tile(sbase, kt + 2, ldst, bm, bn, tid);
        CP_COMMIT();

        const uint32_t stA = sbase + st * STAGE_B;
#pragma unroll
        for (int k16 = 0; k16 < 4; k16++) {
            const int kB = k16 * 32;
            uint32_t a[4][4];
#pragma unroll
            for (int tm = 0; tm < 4; tm++)
                ldmatrix4(a[tm][0], a[tm][1], a[tm][2], a[tm][3], stA + aOff[tm] + kB);
            uint32_t b[8][2];
#pragma unroll
            for (int tp = 0; tp < 4; tp++) {
                uint32_t r0, r1, r2, r3;
                ldmatrix4(r0, r1, r2, r3, stA + bOff[tp] + kB);
                b[tp * 2 + 0][0] = r0; b[tp * 2 + 0][1] = r1;
                b[tp * 2 + 1][0] = r2; b[tp * 2 + 1][1] = r3;
            }
#pragma unroll
            for (int tm = 0; tm < 4; tm++)
#pragma unroll
                for (int tn = 0; tn < 8; tn++)
                    mma16816(acc[tm][tn], a[tm][0], a[tm][1], a[tm][2], a[tm][3],
                             b[tn][0], b[tn][1]);
        }
        st   = (st   == 2) ? 0 : st + 1;
        ldst = (ldst == 2) ? 0 : ldst + 1;
        CP_WAIT1();
        __syncthreads();
    }

    // Epilogue: bias + relu, split to bf16 hi/lo pair -> g_hs
    uint32_t* hp = (uint32_t*)g_hs;    // u32 view: row stride 2048
    const int gid = lane >> 2;
    const int tig = lane & 3;
#pragma unroll
    for (int tn = 0; tn < 8; tn++) {
        const int col = bn + wn + tn * 8 + tig * 2;      // even
        const float bv0 = __ldg(&b1[col]);
        const float bv1 = __ldg(&b1[col + 1]);
#pragma unroll
        for (int tm = 0; tm < 4; tm++) {
            const int row0 = bm + wm + tm * 16 + gid;
#pragma unroll
            for (int hh = 0; hh < 2; hh++) {
                const int row = row0 + hh * 8;
                const float v0 = fmaxf(acc[tm][tn][hh * 2 + 0] + bv0, 0.0f);
                const float v1 = fmaxf(acc[tm][tn][hh * 2 + 1] + bv1, 0.0f);
                uint16_t h0, l0, h1, l1;
                split2(v0, h0, l0);
                split2(v1, h1, l1);
                const size_t base = (size_t)row * 2048 + (col >> 1);
                hp[base]        = (uint32_t)h0 | ((uint32_t)h1 << 16);
                hp[base + 1024] = (uint32_t)l0 | ((uint32_t)l1 << 16);
            }
        }
    }
}

// ---------------------------------------------------------------------------
// Router on HMMA (proven R10): logits = h @ W2^T via 3-pass split (hi/lo
// co-resident), M=64 x N=64 x K=2048 per block; 4 warps, 4-stage cp.async.
// ---------------------------------------------------------------------------
#define R_NSTAGE 4
#define R_ROWB 144
#define R_STAGE (128 * R_ROWB)              // 18432
#define R_NT (H_ / 32)                      // 64
#define R_SMEM_STAGES (R_NSTAGE * R_STAGE)  // 73728
#define R_OFF_LOGITS R_SMEM_STAGES
#define R_OFF_ENT    (R_OFF_LOGITS + 64 * 65 * 4)
#define R_OFF_B2     (R_OFF_ENT + 256)
#define R_SMEM_TOTAL (R_OFF_B2 + 256)       // 91136

__device__ __forceinline__ void load_tile_r(uint32_t sbase, int kk, int st,
                                            int bm, int tid) {
    const uint32_t stg = sbase + st * R_STAGE;
#pragma unroll
    for (int j = 0; j < 8; j++) {
        const int c = tid + (j << 7);
        const int r   = c >> 3;
        const int seg = c & 7;
        const int sel = seg >> 2;
        const int col = sel * H_ + kk * 32 + (seg & 3) * 8;
        const __nv_bfloat16* g = (r < 64)
            ? g_hs  + (size_t)(bm + r) * (2 * H_) + col
            : g_w2s + (size_t)(r - 64) * (2 * H_) + col;
        cp16(stg + r * R_ROWB + seg * 16, g);
    }
}

__global__ __launch_bounds__(128, 2) void router_kernel(
    const float* __restrict__ b2, float* __restrict__ out)
{
    extern __shared__ char smem[];
    const uint32_t sbase = smem_u32(smem);
    float (*logits)[65] = (float (*)[65])(smem + R_OFF_LOGITS);
    float* entbuf = (float*)(smem + R_OFF_ENT);
    float* b2s    = (float*)(smem + R_OFF_B2);

    const int tid  = threadIdx.x;
    const int wid  = tid >> 5;
    const int lane = tid & 31;
    const int bm = blockIdx.x * 64;
    const int wm = wid * 16;

    if (tid < E_) b2s[tid] = b2[tid];

    float acc[8][4];
#pragma unroll
    for (int j = 0; j < 8; j++)
#pragma unroll
        for (int k = 0; k < 4; k++) acc[j][k] = 0.0f;

    load_tile_r(sbase, 0, 0, bm, tid); CP_COMMIT();
    load_tile_r(sbase, 1, 1, bm, tid); CP_COMMIT();
    load_tile_r(sbase, 2, 2, bm, tid); CP_COMMIT();

    const uint32_t aOff = (wm + (lane & 15)) * R_ROWB + (lane >> 4) * 16;
    const int bRow  = (lane & 7) + ((lane >> 4) & 1) * 8;
    const int bColB = ((lane >> 3) & 1) * 16;
    uint32_t bOff[4];
#pragma unroll
    for (int tp = 0; tp < 4; tp++)
        bOff[tp] = 64 * R_ROWB + (bRow + tp * 16) * R_ROWB + bColB;

    CP_WAIT2();
    __syncthreads();

    int st = 0, ldst = 3;
    for (int kt = 0; kt < R_NT; kt++) {
        if (kt + 3 < R_NT) load_tile_r(sbase, kt + 3, ldst, bm, tid);
        CP_COMMIT();

        const uint32_t stg = sbase + st * R_STAGE;
#pragma unroll
        for (int cb = 0; cb < 3; cb++) {
            const int aS = (cb == 2) ? 64 : 0;
            const int bS = (cb == 1) ? 64 : 0;
#pragma unroll
            for (int k16 = 0; k16 < 2; k16++) {
                const int kB = k16 * 32;
                uint32_t a0, a1, a2, a3;
                ldmatrix4(a0, a1, a2, a3, stg + aOff + aS + kB);
                uint32_t b[8][2];
#pragma unroll
                for (int tp = 0; tp < 4; tp++) {
                    uint32_t r0, r1, r2, r3;
                    ldmatrix4(r0, r1, r2, r3, stg + bOff[tp] + bS + kB);
                    b[tp * 2 + 0][0] = r0; b[tp * 2 + 0][1] = r1;
                    b[tp * 2 + 1][0] = r2; b[tp * 2 + 1][1] = r3;
                }
#pragma unroll
                for (int tn = 0; tn < 8; tn++)
                    mma16816(acc[tn], a0, a1, a2, a3, b[tn][0], b[tn][1]);
            }
        }
        st   = (st   == 3) ? 0 : st + 1;
        ldst = (ldst == 3) ? 0 : ldst + 1;
        CP_WAIT2();
        __syncthreads();
    }

    const int gid = lane >> 2;
    const int tig = lane & 3;
#pragma unroll
    for (int tn = 0; tn < 8; tn++) {
        const int e = tn * 8 + tig * 2;
        logits[wm + gid][e]         = acc[tn][0];
        logits[wm + gid][e + 1]     = acc[tn][1];
        logits[wm + gid + 8][e]     = acc[tn][2];
        logits[wm + gid + 8][e + 1] = acc[tn][3];
    }
    __syncthreads();

    if (tid < 64) {
        const int row = tid;
        float l[E_];
        float lmax = -INFINITY;
#pragma unroll
        for (int e = 0; e < E_; e++) {
            l[e] = logits[row][e] + b2s[e];
            lmax = fmaxf(lmax, l[e]);
        }
        int i1 = 0; float v1 = l[0];
#pragma unroll
        for (int e = 1; e < E_; e++)
            if (l[e] > v1) { v1 = l[e]; i1 = e; }
        int i2 = -1; float v2 = -INFINITY;
#pragma unroll
        for (int e = 0; e < E_; e++)
            if (e != i1 && l[e] > v2) { v2 = l[e]; i2 = e; }

        const float e1 = expf((v1 - lmax) * TEMP_INV);
        const float e2 = expf((v2 - lmax) * TEMP_INV);
        const float inv = 1.0f / (e1 + e2);

        float S = 0.0f;
#pragma unroll
        for (int e = 0; e < E_; e++) S += expf(l[e] - lmax);
        const float invS = 1.0f / S;
        float ent = 0.0f;
#pragma unroll
        for (int e = 0; e < E_; e++) {
            const float p = expf(l[e] - lmax) * invS;
            ent -= p * logf(p + 1e-10f);
        }

        const size_t grow = (size_t)bm + row;
        out[grow * 2 + 0] = e1 * inv;
        out[grow * 2 + 1] = e2 * inv;
        out[(size_t)B_ * K_ + grow * 2 + 0] = (float)i1;
        out[(size_t)B_ * K_ + grow * 2 + 1] = (float)i2;
        entbuf[tid] = ent;
    }
    __syncthreads();
    if (tid == 0) {
        float s2 = 0.0f;
#pragma unroll
        for (int r = 0; r < 64; r++) s2 += entbuf[r];
        g_ent[blockIdx.x] = s2;
    }
}

// ---------------------------------------------------------------------------
// Finalize: deterministic entropy reduction (fixed-order tree)
// ---------------------------------------------------------------------------
__global__ void finalize_kernel(float* __restrict__ out)
{
    const int lane = threadIdx.x;   // 32 threads
    float s = 0.0f;
#pragma unroll
    for (int i = 0; i < 8; i++) s += g_ent[lane * 8 + i];
#pragma unroll
    for (int off = 16; off; off >>= 1)
        s += __shfl_down_sync(0xFFFFFFFFu, s, off);
    if (lane == 0)
        out[(size_t)2 * B_ * K_] = s / (float)B_ / logf((float)E_);
}

// ---------------------------------------------------------------------------
extern "C" void kernel_launch(void* const* d_in, const int* in_sizes, int n_in,
                              void* d_out, int out_size)
{
    const float* x  = (const float*)d_in[0];
    const float* W1 = (const float*)d_in[1];
    const float* b1 = (const float*)d_in[2];
    const float* W2 = (const float*)d_in[3];
    const float* b2 = (const float*)d_in[4];
    float* out = (float*)d_out;

    cudaFuncSetAttribute(gemm1_mma_kernel,
                         cudaFuncAttributeMaxDynamicSharedMemorySize, GEMM_SMEM);
    cudaFuncSetAttribute(router_kernel,
                         cudaFuncAttributeMaxDynamicSharedMemorySize, R_SMEM_TOTAL);

    split_both_kernel<<<SPLIT_NB, 256>>>(x, W1, W2);

    dim3 g1(B_ / TM, H_ / TN);   // (128, 8)
    gemm1_mma_kernel<<<g1, 256, GEMM_SMEM>>>(b1);

    router_kernel<<<B_ / 64, 128, R_SMEM_TOTAL>>>(b2, out);
    finalize_kernel<<<1, 32>>>(out);
}

// round 13
// speedup vs baseline: 1.1911x; 1.1911x over previous
#include <cuda_runtime.h>
#include <cuda_bf16.h>
#include <math.h>
#include <stdint.h>

#define B_ 16384
#define D_ 4096
#define H_ 2048
#define E_ 64
#define K_ 2
#define TEMP_INV 1.25f   // 1/0.8

// ---------------------------------------------------------------------------
// Scratch (device globals; no allocs allowed)
// ---------------------------------------------------------------------------
__device__ float g_ent[B_ / 64];
__device__ __nv_bfloat16 g_xs[(size_t)B_ * 2 * D_];    // x split  [B][hi D|lo D]
__device__ __nv_bfloat16 g_ws[(size_t)H_ * 2 * D_];    // W1 split [H][hi D|lo D]
__device__ __nv_bfloat16 g_hs[(size_t)B_ * 2 * H_];    // h split  [B][hi H|lo H]
__device__ __nv_bfloat16 g_w2s[(size_t)E_ * 2 * H_];   // W2 split [E][hi H|lo H]

// ---------------------------------------------------------------------------
// Split helpers: 2-way bf16 decomposition v = hi + lo
// ---------------------------------------------------------------------------
__device__ __forceinline__ void split2(float v, uint16_t& h, uint16_t& l) {
    __nv_bfloat16 hb = __float2bfloat16_rn(v);
    float r = v - __bfloat162float(hb);
    __nv_bfloat16 lb = __float2bfloat16_rn(r);
    h = __bfloat16_as_ushort(hb);
    l = __bfloat16_as_ushort(lb);
}

__device__ __forceinline__ void split2_body(const float* __restrict__ src,
                                            __nv_bfloat16* __restrict__ dst,
                                            int rows, int cols,
                                            int bid, int nblocks) {
    const size_t n4 = (size_t)rows * cols / 4;
    for (size_t i = (size_t)bid * blockDim.x + threadIdx.x; i < n4;
         i += (size_t)nblocks * blockDim.x) {
        const int r = (int)(i / (cols / 4));
        const int c = (int)(i % (cols / 4)) * 4;
        float4 v = *(const float4*)(src + (size_t)r * cols + c);
        uint16_t h[4], l[4];
        split2(v.x, h[0], l[0]);
        split2(v.y, h[1], l[1]);
        split2(v.z, h[2], l[2]);
        split2(v.w, h[3], l[3]);
        __nv_bfloat16* row = dst + (size_t)r * (2 * cols);
        uint2 uh = {(uint32_t)h[0] | ((uint32_t)h[1] << 16),
                    (uint32_t)h[2] | ((uint32_t)h[3] << 16)};
        uint2 ul = {(uint32_t)l[0] | ((uint32_t)l[1] << 16),
                    (uint32_t)l[2] | ((uint32_t)l[3] << 16)};
        *(uint2*)(row + c)        = uh;
        *(uint2*)(row + cols + c) = ul;
    }
}

#define SPLIT_XB 2048
#define SPLIT_W1 248
#define SPLIT_NB 2304   // x:2048, W1:248, W2:8
__global__ __launch_bounds__(256) void split_both_kernel(
    const float* __restrict__ x, const float* __restrict__ W1,
    const float* __restrict__ W2) {
    if (blockIdx.x < SPLIT_XB)
        split2_body(x, g_xs, B_, D_, blockIdx.x, SPLIT_XB);
    else if (blockIdx.x < SPLIT_XB + SPLIT_W1)
        split2_body(W1, g_ws, H_, D_, blockIdx.x - SPLIT_XB, SPLIT_W1);
    else
        split2_body(W2, g_w2s, E_, H_, blockIdx.x - SPLIT_XB - SPLIT_W1,
                    SPLIT_NB - SPLIT_XB - SPLIT_W1);
}

// ---------------------------------------------------------------------------
// Common MMA / async primitives
// ---------------------------------------------------------------------------
__device__ __forceinline__ void cp16(uint32_t smem, const void* g) {
    asm volatile("cp.async.cg.shared.global [%0], [%1], 16;"
                 :: "r"(smem), "l"(g) : "memory");
}
#define CP_COMMIT() asm volatile("cp.async.commit_group;" ::: "memory")
#define CP_WAIT1()  asm volatile("cp.async.wait_group 1;" ::: "memory")
#define CP_WAIT2()  asm volatile("cp.async.wait_group 2;" ::: "memory")

__device__ __forceinline__ void ldmatrix4(uint32_t& r0, uint32_t& r1,
                                          uint32_t& r2, uint32_t& r3, uint32_t a) {
    asm volatile("ldmatrix.sync.aligned.m8n8.x4.shared.b16 {%0,%1,%2,%3}, [%4];"
                 : "=r"(r0), "=r"(r1), "=r"(r2), "=r"(r3) : "r"(a));
}

__device__ __forceinline__ void mma16816(float* c, uint32_t a0, uint32_t a1,
                                         uint32_t a2, uint32_t a3,
                                         uint32_t b0, uint32_t b1) {
    asm volatile(
        "mma.sync.aligned.m16n8k16.row.col.f32.bf16.bf16.f32 "
        "{%0,%1,%2,%3}, {%4,%5,%6,%7}, {%8,%9}, {%0,%1,%2,%3};"
        : "+f"(c[0]), "+f"(c[1]), "+f"(c[2]), "+f"(c[3])
        : "r"(a0), "r"(a1), "r"(a2), "r"(a3), "r"(b0), "r"(b1));
}

__device__ __forceinline__ uint32_t smem_u32(const void* p) {
    uint32_t a;
    asm("{ .reg .u64 t; cvta.to.shared.u64 t, %1; cvt.u32.u64 %0, t; }"
        : "=r"(a) : "l"(p));
    return a;
}

// ---------------------------------------------------------------------------
// GEMM1: h = relu(xh*wh + xh*wl + xl*wh + b1).
// CTA 128x128, 4 warps (64x64 warp tiles, R11 proven), 2 CTAs/SM,
// hi/lo CO-RESIDENT stages: each stage row = [hi 64B | lo 64B] covering 32
// K-cols of both operands; 3 combo passes run off one residency.
// Same MMA/LDSM count as R11 flat 3-pass; 33% fewer global loads + STS,
// 128 vs 192 sync points. 3-stage cp.async. Epilogue stores split h.
// ---------------------------------------------------------------------------
#define TM 128
#define TN 128
#define NSTAGE 3
#define ROWB 144
#define STAGE_B (256 * ROWB)            // 36864
#define GEMM_SMEM (NSTAGE * STAGE_B)    // 110592
#define NT (D_ / 32)                    // 128 k-slices of 32 cols

__device__ __forceinline__ void load_tile(uint32_t sbase, int kk, int st,
                                          int bm, int bn, int tid) {
    const uint32_t stA = sbase + st * STAGE_B;
    const uint32_t stB = stA + 128 * ROWB;
#pragma unroll
    for (int j = 0; j < 16; j++) {
        const int c   = tid + (j << 7);       // 0..2047 (128 threads x 16)
        const int r   = (c >> 3) & 127;
        const int seg = c & 7;
        const int sel = seg >> 2;             // 0 = hi, 1 = lo
        const int col = sel * D_ + kk * 32 + (seg & 3) * 8;
        if (c < 1024) {
            const __nv_bfloat16* g = g_xs + (size_t)(bm + r) * (2 * D_) + col;
            cp16(stA + r * ROWB + seg * 16, g);
        } else {
            const __nv_bfloat16* g = g_ws + (size_t)(bn + r) * (2 * D_) + col;
            cp16(stB + r * ROWB + seg * 16, g);
        }
    }
}

__global__ __launch_bounds__(128, 2) void gemm1_mma_kernel(const float* __restrict__ b1) {
    extern __shared__ char smem[];
    const uint32_t sbase = smem_u32(smem);
    const int tid  = threadIdx.x;
    const int wid  = tid >> 5;
    const int lane = tid & 31;
    const int bm = blockIdx.x * TM;
    const int bn = blockIdx.y * TN;
    const int wm = (wid & 1) * 64;      // 2 warps in M
    const int wn = (wid >> 1) * 64;     // 2 warps in N

    float acc[4][8][4];
#pragma unroll
    for (int i = 0; i < 4; i++)
#pragma unroll
        for (int j = 0; j < 8; j++)
#pragma unroll
            for (int k = 0; k < 4; k++) acc[i][j][k] = 0.0f;

    load_tile(sbase, 0, 0, bm, bn, tid); CP_COMMIT();
    load_tile(sbase, 1, 1, bm, bn, tid); CP_COMMIT();

    const int aRow  = wm + (lane & 15);
    const int aColB = (lane >> 4) * 16;
    const int bRow  = wn + (lane & 7) + ((lane >> 4) & 1) * 8;
    const int bColB = ((lane >> 3) & 1) * 16;
    uint32_t aOff[4], bOff[4];
#pragma unroll
    for (int tm = 0; tm < 4; tm++) aOff[tm] = (aRow + tm * 16) * ROWB + aColB;
#pragma unroll
    for (int tp = 0; tp < 4; tp++) bOff[tp] = 128 * ROWB + (bRow + tp * 16) * ROWB + bColB;

    CP_WAIT1();
    __syncthreads();

    int st = 0, ldst = 2;
    for (int kt = 0; kt < NT; kt++) {
        if (kt + 2 < NT) load_tile(sbase, kt + 2, ldst, bm, bn, tid);
        CP_COMMIT();

        const uint32_t stA = sbase + st * STAGE_B;
        // 3 combos off one residency: (Ah,Bh), (Ah,Bl), (Al,Bh)
#pragma unroll
        for (int cb = 0; cb < 3; cb++) {
            const int aS = (cb == 2) ? 64 : 0;
            const int bS = (cb == 1) ? 64 : 0;
#pragma unroll
            for (int k16 = 0; k16 < 2; k16++) {
                const int kB = k16 * 32;
                uint32_t a[4][4];
#pragma unroll
                for (int tm = 0; tm < 4; tm++)
                    ldmatrix4(a[tm][0], a[tm][1], a[tm][2], a[tm][3],
                              stA + aOff[tm] + aS + kB);
                uint32_t b[8][2];
#pragma unroll
                for (int tp = 0; tp < 4; tp++) {
                    uint32_t r0, r1, r2, r3;
                    ldmatrix4(r0, r1, r2, r3, stA + bOff[tp] + bS + kB);
                    b[tp * 2 + 0][0] = r0; b[tp * 2 + 0][1] = r1;
                    b[tp * 2 + 1][0] = r2; b[tp * 2 + 1][1] = r3;
                }
#pragma unroll
                for (int tm = 0; tm < 4; tm++)
#pragma unroll
                    for (int tn = 0; tn < 8; tn++)
                        mma16816(acc[tm][tn], a[tm][0], a[tm][1], a[tm][2], a[tm][3],
                                 b[tn][0], b[tn][1]);
            }
        }
        st   = (st   == 2) ? 0 : st + 1;
        ldst = (ldst == 2) ? 0 : ldst + 1;
        CP_WAIT1();
        __syncthreads();
    }

    // Epilogue: bias + relu, split to bf16 hi/lo pair -> g_hs
    uint32_t* hp = (uint32_t*)g_hs;    // u32 view: row stride 2048
    const int gid = lane >> 2;
    const int tig = lane & 3;
#pragma unroll
    for (int tn = 0; tn < 8; tn++) {
        const int col = bn + wn + tn * 8 + tig * 2;      // even
        const float bv0 = __ldg(&b1[col]);
        const float bv1 = __ldg(&b1[col + 1]);
#pragma unroll
        for (int tm = 0; tm < 4; tm++) {
            const int row0 = bm + wm + tm * 16 + gid;
#pragma unroll
            for (int hh = 0; hh < 2; hh++) {
                const int row = row0 + hh * 8;
                const float v0 = fmaxf(acc[tm][tn][hh * 2 + 0] + bv0, 0.0f);
                const float v1 = fmaxf(acc[tm][tn][hh * 2 + 1] + bv1, 0.0f);
                uint16_t h0, l0, h1, l1;
                split2(v0, h0, l0);
                split2(v1, h1, l1);
                const size_t base = (size_t)row * 2048 + (col >> 1);
                hp[base]        = (uint32_t)h0 | ((uint32_t)h1 << 16);
                hp[base + 1024] = (uint32_t)l0 | ((uint32_t)l1 << 16);
            }
        }
    }
}

// ---------------------------------------------------------------------------
// Router on HMMA (proven R10): logits = h @ W2^T via 3-pass split (hi/lo
// co-resident), M=64 x N=64 x K=2048 per block; 4 warps, 4-stage cp.async.
// ---------------------------------------------------------------------------
#define R_NSTAGE 4
#define R_ROWB 144
#define R_STAGE (128 * R_ROWB)              // 18432
#define R_NT (H_ / 32)                      // 64
#define R_SMEM_STAGES (R_NSTAGE * R_STAGE)  // 73728
#define R_OFF_LOGITS R_SMEM_STAGES
#define R_OFF_ENT    (R_OFF_LOGITS + 64 * 65 * 4)
#define R_OFF_B2     (R_OFF_ENT + 256)
#define R_SMEM_TOTAL (R_OFF_B2 + 256)       // 91136

__device__ __forceinline__ void load_tile_r(uint32_t sbase, int kk, int st,
                                            int bm, int tid) {
    const uint32_t stg = sbase + st * R_STAGE;
#pragma unroll
    for (int j = 0; j < 8; j++) {
        const int c = tid + (j << 7);
        const int r   = c >> 3;
        const int seg = c & 7;
        const int sel = seg >> 2;
        const int col = sel * H_ + kk * 32 + (seg & 3) * 8;
        const __nv_bfloat16* g = (r < 64)
            ? g_hs  + (size_t)(bm + r) * (2 * H_) + col
            : g_w2s + (size_t)(r - 64) * (2 * H_) + col;
        cp16(stg + r * R_ROWB + seg * 16, g);
    }
}

__global__ __launch_bounds__(128, 2) void router_kernel(
    const float* __restrict__ b2, float* __restrict__ out)
{
    extern __shared__ char smem[];
    const uint32_t sbase = smem_u32(smem);
    float (*logits)[65] = (float (*)[65])(smem + R_OFF_LOGITS);
    float* entbuf = (float*)(smem + R_OFF_ENT);
    float* b2s    = (float*)(smem + R_OFF_B2);

    const int tid  = threadIdx.x;
    const int wid  = tid >> 5;
    const int lane = tid & 31;
    const int bm = blockIdx.x * 64;
    const int wm = wid * 16;

    if (tid < E_) b2s[tid] = b2[tid];

    float acc[8][4];
#pragma unroll
    for (int j = 0; j < 8; j++)
#pragma unroll
        for (int k = 0; k < 4; k++) acc[j][k] = 0.0f;

    load_tile_r(sbase, 0, 0, bm, tid); CP_COMMIT();
    load_tile_r(sbase, 1, 1, bm, tid); CP_COMMIT();
    load_tile_r(sbase, 2, 2, bm, tid); CP_COMMIT();

    const uint32_t aOff = (wm + (lane & 15)) * R_ROWB + (lane >> 4) * 16;
    const int bRow  = (lane & 7) + ((lane >> 4) & 1) * 8;
    const int bColB = ((lane >> 3) & 1) * 16;
    uint32_t bOff[4];
#pragma unroll
    for (int tp = 0; tp < 4; tp++)
        bOff[tp] = 64 * R_ROWB + (bRow + tp * 16) * R_ROWB + bColB;

    CP_WAIT2();
    __syncthreads();

    int st = 0, ldst = 3;
    for (int kt = 0; kt < R_NT; kt++) {
        if (kt + 3 < R_NT) load_tile_r(sbase, kt + 3, ldst, bm, tid);
        CP_COMMIT();

        const uint32_t stg = sbase + st * R_STAGE;
#pragma unroll
        for (int cb = 0; cb < 3; cb++) {
            const int aS = (cb == 2) ? 64 : 0;
            const int bS = (cb == 1) ? 64 : 0;
#pragma unroll
            for (int k16 = 0; k16 < 2; k16++) {
                const int kB = k16 * 32;
                uint32_t a0, a1, a2, a3;
                ldmatrix4(a0, a1, a2, a3, stg + aOff + aS + kB);
                uint32_t b[8][2];
#pragma unroll
                for (int tp = 0; tp < 4; tp++) {
                    uint32_t r0, r1, r2, r3;
                    ldmatrix4(r0, r1, r2, r3, stg + bOff[tp] + bS + kB);
                    b[tp * 2 + 0][0] = r0; b[tp * 2 + 0][1] = r1;
                    b[tp * 2 + 1][0] = r2; b[tp * 2 + 1][1] = r3;
                }
#pragma unroll
                for (int tn = 0; tn < 8; tn++)
                    mma16816(acc[tn], a0, a1, a2, a3, b[tn][0], b[tn][1]);
            }
        }
        st   = (st   == 3) ? 0 : st + 1;
        ldst = (ldst == 3) ? 0 : ldst + 1;
        CP_WAIT2();
        __syncthreads();
    }

    const int gid = lane >> 2;
    const int tig = lane & 3;
#pragma unroll
    for (int tn = 0; tn < 8; tn++) {
        const int e = tn * 8 + tig * 2;
        logits[wm + gid][e]         = acc[tn][0];
        logits[wm + gid][e + 1]     = acc[tn][1];
        logits[wm + gid + 8][e]     = acc[tn][2];
        logits[wm + gid + 8][e + 1] = acc[tn][3];
    }
    __syncthreads();

    if (tid < 64) {
        const int row = tid;
        float l[E_];
        float lmax = -INFINITY;
#pragma unroll
        for (int e = 0; e < E_; e++) {
            l[e] = logits[row][e] + b2s[e];
            lmax = fmaxf(lmax, l[e]);
        }
        int i1 = 0; float v1 = l[0];
#pragma unroll
        for (int e = 1; e < E_; e++)
            if (l[e] > v1) { v1 = l[e]; i1 = e; }
        int i2 = -1; float v2 = -INFINITY;
#pragma unroll
        for (int e = 0; e < E_; e++)
            if (e != i1 && l[e] > v2) { v2 = l[e]; i2 = e; }

        const float e1 = expf((v1 - lmax) * TEMP_INV);
        const float e2 = expf((v2 - lmax) * TEMP_INV);
        const float inv = 1.0f / (e1 + e2);

        float S = 0.0f;
#pragma unroll
        for (int e = 0; e < E_; e++) S += expf(l[e] - lmax);
        const float invS = 1.0f / S;
        float ent = 0.0f;
#pragma unroll
        for (int e = 0; e < E_; e++) {
            const float p = expf(l[e] - lmax) * invS;
            ent -= p * logf(p + 1e-10f);
        }

        const size_t grow = (size_t)bm + row;
        out[grow * 2 + 0] = e1 * inv;
        out[grow * 2 + 1] = e2 * inv;
        out[(size_t)B_ * K_ + grow * 2 + 0] = (float)i1;
        out[(size_t)B_ * K_ + grow * 2 + 1] = (float)i2;
        entbuf[tid] = ent;
    }
    __syncthreads();
    if (tid == 0) {
        float s2 = 0.0f;
#pragma unroll
        for (int r = 0; r < 64; r++) s2 += entbuf[r];
        g_ent[blockIdx.x] = s2;
    }
}

// ---------------------------------------------------------------------------
// Finalize: deterministic entropy reduction (fixed-order tree)
// ---------------------------------------------------------------------------
__global__ void finalize_kernel(float* __restrict__ out)
{
    const int lane = threadIdx.x;   // 32 threads
    float s = 0.0f;
#pragma unroll
    for (int i = 0; i < 8; i++) s += g_ent[lane * 8 + i];
#pragma unroll
    for (int off = 16; off; off >>= 1)
        s += __shfl_down_sync(0xFFFFFFFFu, s, off);
    if (lane == 0)
        out[(size_t)2 * B_ * K_] = s / (float)B_ / logf((float)E_);
}

// ---------------------------------------------------------------------------
extern "C" void kernel_launch(void* const* d_in, const int* in_sizes, int n_in,
                              void* d_out, int out_size)
{
    const float* x  = (const float*)d_in[0];
    const float* W1 = (const float*)d_in[1];
    const float* b1 = (const float*)d_in[2];
    const float* W2 = (const float*)d_in[3];
    const float* b2 = (const float*)d_in[4];
    float* out = (float*)d_out;

    cudaFuncSetAttribute(gemm1_mma_kernel,
                         cudaFuncAttributeMaxDynamicSharedMemorySize, GEMM_SMEM);
    cudaFuncSetAttribute(router_kernel,
                         cudaFuncAttributeMaxDynamicSharedMemorySize, R_SMEM_TOTAL);

    split_both_kernel<<<SPLIT_NB, 256>>>(x, W1, W2);

    dim3 g1(B_ / TM, H_ / TN);   // (128, 16)
    gemm1_mma_kernel<<<g1, 128, GEMM_SMEM>>>(b1);

    router_kernel<<<B_ / 64, 128, R_SMEM_TOTAL>>>(b2, out);
    finalize_kernel<<<1, 32>>>(out);
}

// round 14
// speedup vs baseline: 1.1945x; 1.0029x over previous
#include <cuda_runtime.h>
#include <cuda_bf16.h>
#include <math.h>
#include <stdint.h>

#define B_ 16384
#define D_ 4096
#define H_ 2048
#define E_ 64
#define K_ 2
#define TEMP_INV 1.25f   // 1/0.8

// ---------------------------------------------------------------------------
// Scratch (device globals; no allocs allowed)
// ---------------------------------------------------------------------------
__device__ float g_ent[B_ / 64];
__device__ __nv_bfloat16 g_xs[(size_t)B_ * 2 * D_];    // x split  [B][hi D|lo D]
__device__ __nv_bfloat16 g_ws[(size_t)H_ * 2 * D_];    // W1 split [H][hi D|lo D]
__device__ __nv_bfloat16 g_hs[(size_t)B_ * 2 * H_];    // h split  [B][hi H|lo H]
__device__ __nv_bfloat16 g_w2s[(size_t)E_ * 2 * H_];   // W2 split [E][hi H|lo H]

// ---------------------------------------------------------------------------
// Split helpers: 2-way bf16 decomposition v = hi + lo
// ---------------------------------------------------------------------------
__device__ __forceinline__ void split2(float v, uint16_t& h, uint16_t& l) {
    __nv_bfloat16 hb = __float2bfloat16_rn(v);
    float r = v - __bfloat162float(hb);
    __nv_bfloat16 lb = __float2bfloat16_rn(r);
    h = __bfloat16_as_ushort(hb);
    l = __bfloat16_as_ushort(lb);
}

// 8 elements per thread: 2x float4 loads -> 1x uint4 hi store + 1x uint4 lo.
__device__ __forceinline__ void split2_body(const float* __restrict__ src,
                                            __nv_bfloat16* __restrict__ dst,
                                            int rows, int cols,
                                            int bid, int nblocks) {
    const size_t n8 = (size_t)rows * cols / 8;
    for (size_t i = (size_t)bid * blockDim.x + threadIdx.x; i < n8;
         i += (size_t)nblocks * blockDim.x) {
        const int r = (int)(i / (cols / 8));
        const int c = (int)(i % (cols / 8)) * 8;
        const float* sp = src + (size_t)r * cols + c;
        float4 v0 = *(const float4*)(sp);
        float4 v1 = *(const float4*)(sp + 4);
        uint16_t h[8], l[8];
        split2(v0.x, h[0], l[0]); split2(v0.y, h[1], l[1]);
        split2(v0.z, h[2], l[2]); split2(v0.w, h[3], l[3]);
        split2(v1.x, h[4], l[4]); split2(v1.y, h[5], l[5]);
        split2(v1.z, h[6], l[6]); split2(v1.w, h[7], l[7]);
        __nv_bfloat16* row = dst + (size_t)r * (2 * cols);
        uint4 uh, ul;
        uh.x = (uint32_t)h[0] | ((uint32_t)h[1] << 16);
        uh.y = (uint32_t)h[2] | ((uint32_t)h[3] << 16);
        uh.z = (uint32_t)h[4] | ((uint32_t)h[5] << 16);
        uh.w = (uint32_t)h[6] | ((uint32_t)h[7] << 16);
        ul.x = (uint32_t)l[0] | ((uint32_t)l[1] << 16);
        ul.y = (uint32_t)l[2] | ((uint32_t)l[3] << 16);
        ul.z = (uint32_t)l[4] | ((uint32_t)l[5] << 16);
        ul.w = (uint32_t)l[6] | ((uint32_t)l[7] << 16);
        *(uint4*)(row + c)        = uh;
        *(uint4*)(row + cols + c) = ul;
    }
}

#define SPLIT_XB 2048
#define SPLIT_W1 248
#define SPLIT_NB 2304   // x:2048, W1:248, W2:8
__global__ __launch_bounds__(256) void split_both_kernel(
    const float* __restrict__ x, const float* __restrict__ W1,
    const float* __restrict__ W2) {
    if (blockIdx.x < SPLIT_XB)
        split2_body(x, g_xs, B_, D_, blockIdx.x, SPLIT_XB);
    else if (blockIdx.x < SPLIT_XB + SPLIT_W1)
        split2_body(W1, g_ws, H_, D_, blockIdx.x - SPLIT_XB, SPLIT_W1);
    else
        split2_body(W2, g_w2s, E_, H_, blockIdx.x - SPLIT_XB - SPLIT_W1,
                    SPLIT_NB - SPLIT_XB - SPLIT_W1);
}

// ---------------------------------------------------------------------------
// Common MMA / async primitives
// ---------------------------------------------------------------------------
__device__ __forceinline__ void cp16(uint32_t smem, const void* g) {
    asm volatile("cp.async.cg.shared.global [%0], [%1], 16;"
                 :: "r"(smem), "l"(g) : "memory");
}
#define CP_COMMIT() asm volatile("cp.async.commit_group;" ::: "memory")
#define CP_WAIT1()  asm volatile("cp.async.wait_group 1;" ::: "memory")
#define CP_WAIT2()  asm volatile("cp.async.wait_group 2;" ::: "memory")

__device__ __forceinline__ void ldmatrix4(uint32_t& r0, uint32_t& r1,
                                          uint32_t& r2, uint32_t& r3, uint32_t a) {
    asm volatile("ldmatrix.sync.aligned.m8n8.x4.shared.b16 {%0,%1,%2,%3}, [%4];"
                 : "=r"(r0), "=r"(r1), "=r"(r2), "=r"(r3) : "r"(a));
}

__device__ __forceinline__ void mma16816(float* c, uint32_t a0, uint32_t a1,
                                         uint32_t a2, uint32_t a3,
                                         uint32_t b0, uint32_t b1) {
    asm volatile(
        "mma.sync.aligned.m16n8k16.row.col.f32.bf16.bf16.f32 "
        "{%0,%1,%2,%3}, {%4,%5,%6,%7}, {%8,%9}, {%0,%1,%2,%3};"
        : "+f"(c[0]), "+f"(c[1]), "+f"(c[2]), "+f"(c[3])
        : "r"(a0), "r"(a1), "r"(a2), "r"(a3), "r"(b0), "r"(b1));
}

__device__ __forceinline__ uint32_t smem_u32(const void* p) {
    uint32_t a;
    asm("{ .reg .u64 t; cvta.to.shared.u64 t, %1; cvt.u32.u64 %0, t; }"
        : "=r"(a) : "l"(p));
    return a;
}

// ---------------------------------------------------------------------------
// GEMM1: h = relu(xh*wh + xh*wl + xl*wh + b1).
// CTA 128x128, 4 warps (64x64 warp tiles), 2 CTAs/SM, hi/lo CO-RESIDENT
// stages (R13 proven). Grid ordered bn-FASTEST so a resident wave covers all
// 16 bn blocks x ~18 bm tiles -> x tiles get their 16x reuse from L2
// (DRAM reads ~4.3GB -> ~0.4GB).
// ---------------------------------------------------------------------------
#define TM 128
#define TN 128
#define NSTAGE 3
#define ROWB 144
#define STAGE_B (256 * ROWB)            // 36864
#define GEMM_SMEM (NSTAGE * STAGE_B)    // 110592
#define NT (D_ / 32)                    // 128 k-slices of 32 cols

__device__ __forceinline__ void load_tile(uint32_t sbase, int kk, int st,
                                          int bm, int bn, int tid) {
    const uint32_t stA = sbase + st * STAGE_B;
    const uint32_t stB = stA + 128 * ROWB;
#pragma unroll
    for (int j = 0; j < 16; j++) {
        const int c   = tid + (j << 7);       // 0..2047 (128 threads x 16)
        const int r   = (c >> 3) & 127;
        const int seg = c & 7;
        const int sel = seg >> 2;             // 0 = hi, 1 = lo
        const int col = sel * D_ + kk * 32 + (seg & 3) * 8;
        if (c < 1024) {
            const __nv_bfloat16* g = g_xs + (size_t)(bm + r) * (2 * D_) + col;
            cp16(stA + r * ROWB + seg * 16, g);
        } else {
            const __nv_bfloat16* g = g_ws + (size_t)(bn + r) * (2 * D_) + col;
            cp16(stB + r * ROWB + seg * 16, g);
        }
    }
}

__global__ __launch_bounds__(128, 2) void gemm1_mma_kernel(const float* __restrict__ b1) {
    extern __shared__ char smem[];
    const uint32_t sbase = smem_u32(smem);
    const int tid  = threadIdx.x;
    const int wid  = tid >> 5;
    const int lane = tid & 31;
    const int bm = blockIdx.y * TM;      // bm on slow axis
    const int bn = blockIdx.x * TN;      // bn on FAST axis (L2 x reuse)
    const int wm = (wid & 1) * 64;       // 2 warps in M
    const int wn = (wid >> 1) * 64;      // 2 warps in N

    float acc[4][8][4];
#pragma unroll
    for (int i = 0; i < 4; i++)
#pragma unroll
        for (int j = 0; j < 8; j++)
#pragma unroll
            for (int k = 0; k < 4; k++) acc[i][j][k] = 0.0f;

    load_tile(sbase, 0, 0, bm, bn, tid); CP_COMMIT();
    load_tile(sbase, 1, 1, bm, bn, tid); CP_COMMIT();

    const int aRow  = wm + (lane & 15);
    const int aColB = (lane >> 4) * 16;
    const int bRow  = wn + (lane & 7) + ((lane >> 4) & 1) * 8;
    const int bColB = ((lane >> 3) & 1) * 16;
    uint32_t aOff[4], bOff[4];
#pragma unroll
    for (int tm = 0; tm < 4; tm++) aOff[tm] = (aRow + tm * 16) * ROWB + aColB;
#pragma unroll
    for (int tp = 0; tp < 4; tp++) bOff[tp] = 128 * ROWB + (bRow + tp * 16) * ROWB + bColB;

    CP_WAIT1();
    __syncthreads();

    int st = 0, ldst = 2;
    for (int kt = 0; kt < NT; kt++) {
        if (kt + 2 < NT) load_tile(sbase, kt + 2, ldst, bm, bn, tid);
        CP_COMMIT();

        const uint32_t stA = sbase + st * STAGE_B;
        // 3 combos off one residency: (Ah,Bh), (Ah,Bl), (Al,Bh)
#pragma unroll
        for (int cb = 0; cb < 3; cb++) {
            const int aS = (cb == 2) ? 64 : 0;
            const int bS = (cb == 1) ? 64 : 0;
#pragma unroll
            for (int k16 = 0; k16 < 2; k16++) {
                const int kB = k16 * 32;
                uint32_t a[4][4];
#pragma unroll
                for (int tm = 0; tm < 4; tm++)
                    ldmatrix4(a[tm][0], a[tm][1], a[tm][2], a[tm][3],
                              stA + aOff[tm] + aS + kB);
                uint32_t b[8][2];
#pragma unroll
                for (int tp = 0; tp < 4; tp++) {
                    uint32_t r0, r1, r2, r3;
                    ldmatrix4(r0, r1, r2, r3, stA + bOff[tp] + bS + kB);
                    b[tp * 2 + 0][0] = r0; b[tp * 2 + 0][1] = r1;
                    b[tp * 2 + 1][0] = r2; b[tp * 2 + 1][1] = r3;
                }
#pragma unroll
                for (int tm = 0; tm < 4; tm++)
#pragma unroll
                    for (int tn = 0; tn < 8; tn++)
                        mma16816(acc[tm][tn], a[tm][0], a[tm][1], a[tm][2], a[tm][3],
                                 b[tn][0], b[tn][1]);
            }
        }
        st   = (st   == 2) ? 0 : st + 1;
        ldst = (ldst == 2) ? 0 : ldst + 1;
        CP_WAIT1();
        __syncthreads();
    }

    // Epilogue: bias + relu, split to bf16 hi/lo pair -> g_hs
    uint32_t* hp = (uint32_t*)g_hs;    // u32 view: row stride 2048
    const int gid = lane >> 2;
    const int tig = lane & 3;
#pragma unroll
    for (int tn = 0; tn < 8; tn++) {
        const int col = bn + wn + tn * 8 + tig * 2;      // even
        const float bv0 = __ldg(&b1[col]);
        const float bv1 = __ldg(&b1[col + 1]);
#pragma unroll
        for (int tm = 0; tm < 4; tm++) {
            const int row0 = bm + wm + tm * 16 + gid;
#pragma unroll
            for (int hh = 0; hh < 2; hh++) {
                const int row = row0 + hh * 8;
                const float v0 = fmaxf(acc[tm][tn][hh * 2 + 0] + bv0, 0.0f);
                const float v1 = fmaxf(acc[tm][tn][hh * 2 + 1] + bv1, 0.0f);
                uint16_t h0, l0, h1, l1;
                split2(v0, h0, l0);
                split2(v1, h1, l1);
                const size_t base = (size_t)row * 2048 + (col >> 1);
                hp[base]        = (uint32_t)h0 | ((uint32_t)h1 << 16);
                hp[base + 1024] = (uint32_t)l0 | ((uint32_t)l1 << 16);
            }
        }
    }
}

// ---------------------------------------------------------------------------
// Router on HMMA (proven R10): logits = h @ W2^T via 3-pass split (hi/lo
// co-resident), M=64 x N=64 x K=2048 per block; 4 warps, 4-stage cp.async.
// ---------------------------------------------------------------------------
#define R_NSTAGE 4
#define R_ROWB 144
#define R_STAGE (128 * R_ROWB)              // 18432
#define R_NT (H_ / 32)                      // 64
#define R_SMEM_STAGES (R_NSTAGE * R_STAGE)  // 73728
#define R_OFF_LOGITS R_SMEM_STAGES
#define R_OFF_ENT    (R_OFF_LOGITS + 64 * 65 * 4)
#define R_OFF_B2     (R_OFF_ENT + 256)
#define R_SMEM_TOTAL (R_OFF_B2 + 256)       // 91136

__device__ __forceinline__ void load_tile_r(uint32_t sbase, int kk, int st,
                                            int bm, int tid) {
    const uint32_t stg = sbase + st * R_STAGE;
#pragma unroll
    for (int j = 0; j < 8; j++) {
        const int c = tid + (j << 7);
        const int r   = c >> 3;
        const int seg = c & 7;
        const int sel = seg >> 2;
        const int col = sel * H_ + kk * 32 + (seg & 3) * 8;
        const __nv_bfloat16* g = (r < 64)
            ? g_hs  + (size_t)(bm + r) * (2 * H_) + col
            : g_w2s + (size_t)(r - 64) * (2 * H_) + col;
        cp16(stg + r * R_ROWB + seg * 16, g);
    }
}

__global__ __launch_bounds__(128, 2) void router_kernel(
    const float* __restrict__ b2, float* __restrict__ out)
{
    extern __shared__ char smem[];
    const uint32_t sbase = smem_u32(smem);
    float (*logits)[65] = (float (*)[65])(smem + R_OFF_LOGITS);
    float* entbuf = (float*)(smem + R_OFF_ENT);
    float* b2s    = (float*)(smem + R_OFF_B2);

    const int tid  = threadIdx.x;
    const int wid  = tid >> 5;
    const int lane = tid & 31;
    const int bm = blockIdx.x * 64;
    const int wm = wid * 16;

    if (tid < E_) b2s[tid] = b2[tid];

    float acc[8][4];
#pragma unroll
    for (int j = 0; j < 8; j++)
#pragma unroll
        for (int k = 0; k < 4; k++) acc[j][k] = 0.0f;

    load_tile_r(sbase, 0, 0, bm, tid); CP_COMMIT();
    load_tile_r(sbase, 1, 1, bm, tid); CP_COMMIT();
    load_tile_r(sbase, 2, 2, bm, tid); CP_COMMIT();

    const uint32_t aOff = (wm + (lane & 15)) * R_ROWB + (lane >> 4) * 16;
    const int bRow  = (lane & 7) + ((lane >> 4) & 1) * 8;
    const int bColB = ((lane >> 3) & 1) * 16;
    uint32_t bOff[4];
#pragma unroll
    for (int tp = 0; tp < 4; tp++)
        bOff[tp] = 64 * R_ROWB + (bRow + tp * 16) * R_ROWB + bColB;

    CP_WAIT2();
    __syncthreads();

    int st = 0, ldst = 3;
    for (int kt = 0; kt < R_NT; kt++) {
        if (kt + 3 < R_NT) load_tile_r(sbase, kt + 3, ldst, bm, tid);
        CP_COMMIT();

        const uint32_t stg = sbase + st * R_STAGE;
#pragma unroll
        for (int cb = 0; cb < 3; cb++) {
            const int aS = (cb == 2) ? 64 : 0;
            const int bS = (cb == 1) ? 64 : 0;
#pragma unroll
            for (int k16 = 0; k16 < 2; k16++) {
                const int kB = k16 * 32;
                uint32_t a0, a1, a2, a3;
                ldmatrix4(a0, a1, a2, a3, stg + aOff + aS + kB);
                uint32_t b[8][2];
#pragma unroll
                for (int tp = 0; tp < 4; tp++) {
                    uint32_t r0, r1, r2, r3;
                    ldmatrix4(r0, r1, r2, r3, stg + bOff[tp] + bS + kB);
                    b[tp * 2 + 0][0] = r0; b[tp * 2 + 0][1] = r1;
                    b[tp * 2 + 1][0] = r2; b[tp * 2 + 1][1] = r3;
                }
#pragma unroll
                for (int tn = 0; tn < 8; tn++)
                    mma16816(acc[tn], a0, a1, a2, a3, b[tn][0], b[tn][1]);
            }
        }
        st   = (st   == 3) ? 0 : st + 1;
        ldst = (ldst == 3) ? 0 : ldst + 1;
        CP_WAIT2();
        __syncthreads();
    }

    const int gid = lane >> 2;
    const int tig = lane & 3;
#pragma unroll
    for (int tn = 0; tn < 8; tn++) {
        const int e = tn * 8 + tig * 2;
        logits[wm + gid][e]         = acc[tn][0];
        logits[wm + gid][e + 1]     = acc[tn][1];
        logits[wm + gid + 8][e]     = acc[tn][2];
        logits[wm + gid + 8][e + 1] = acc[tn][3];
    }
    __syncthreads();

    if (tid < 64) {
        const int row = tid;
        float l[E_];
        float lmax = -INFINITY;
#pragma unroll
        for (int e = 0; e < E_; e++) {
            l[e] = logits[row][e] + b2s[e];
            lmax = fmaxf(lmax, l[e]);
        }
        int i1 = 0; float v1 = l[0];
#pragma unroll
        for (int e = 1; e < E_; e++)
            if (l[e] > v1) { v1 = l[e]; i1 = e; }
        int i2 = -1; float v2 = -INFINITY;
#pragma unroll
        for (int e = 0; e < E_; e++)
            if (e != i1 && l[e] > v2) { v2 = l[e]; i2 = e; }

        const float e1 = expf((v1 - lmax) * TEMP_INV);
        const float e2 = expf((v2 - lmax) * TEMP_INV);
        const float inv = 1.0f / (e1 + e2);

        float S = 0.0f;
#pragma unroll
        for (int e = 0; e < E_; e++) S += expf(l[e] - lmax);
        const float invS = 1.0f / S;
        float ent = 0.0f;
#pragma unroll
        for (int e = 0; e < E_; e++) {
            const float p = expf(l[e] - lmax) * invS;
            ent -= p * logf(p + 1e-10f);
        }

        const size_t grow = (size_t)bm + row;
        out[grow * 2 + 0] = e1 * inv;
        out[grow * 2 + 1] = e2 * inv;
        out[(size_t)B_ * K_ + grow * 2 + 0] = (float)i1;
        out[(size_t)B_ * K_ + grow * 2 + 1] = (float)i2;
        entbuf[tid] = ent;
    }
    __syncthreads();
    if (tid == 0) {
        float s2 = 0.0f;
#pragma unroll
        for (int r = 0; r < 64; r++) s2 += entbuf[r];
        g_ent[blockIdx.x] = s2;
    }
}

// ---------------------------------------------------------------------------
// Finalize: deterministic entropy reduction (fixed-order tree)
// ---------------------------------------------------------------------------
__global__ void finalize_kernel(float* __restrict__ out)
{
    const int lane = threadIdx.x;   // 32 threads
    float s = 0.0f;
#pragma unroll
    for (int i = 0; i < 8; i++) s += g_ent[lane * 8 + i];
#pragma unroll
    for (int off = 16; off; off >>= 1)
        s += __shfl_down_sync(0xFFFFFFFFu, s, off);
    if (lane == 0)
        out[(size_t)2 * B_ * K_] = s / (float)B_ / logf((float)E_);
}

// ---------------------------------------------------------------------------
extern "C" void kernel_launch(void* const* d_in, const int* in_sizes, int n_in,
                              void* d_out, int out_size)
{
    const float* x  = (const float*)d_in[0];
    const float* W1 = (const float*)d_in[1];
    const float* b1 = (const float*)d_in[2];
    const float* W2 = (const float*)d_in[3];
    const float* b2 = (const float*)d_in[4];
    float* out = (float*)d_out;

    cudaFuncSetAttribute(gemm1_mma_kernel,
                         cudaFuncAttributeMaxDynamicSharedMemorySize, GEMM_SMEM);
    cudaFuncSetAttribute(router_kernel,
                         cudaFuncAttributeMaxDynamicSharedMemorySize, R_SMEM_TOTAL);

    split_both_kernel<<<SPLIT_NB, 256>>>(x, W1, W2);

    dim3 g1(H_ / TN, B_ / TM);   // (16, 128): bn fastest -> x L2 reuse
    gemm1_mma_kernel<<<g1, 128, GEMM_SMEM>>>(b1);

    router_kernel<<<B_ / 64, 128, R_SMEM_TOTAL>>>(b2, out);
    finalize_kernel<<<1, 32>>>(out);
}